// round 6
// baseline (speedup 1.0000x reference)
#include <cuda_runtime.h>

#define NB   16384
#define NJ   12
#define NQ   7
#define NO   5
#define NH1  128
#define NH2  128
#define GS   4
#define NBLOCKS (NB / GS)

#define W1_SZ (NQ * (NO + 1) * NH1)     // 5376
#define W2_SZ ((NH1 + 1) * NH2)         // 16512
#define VT_ROW 132                      // [w_1..w_128, bias, 0,0,0]
#define VT_SZ (NQ * NO * VT_ROW)        // 4620
#define ZSTR 36                         // z1 row stride in floats (bank stagger)

#define PREP_BLOCKS 64
#define PREP_THREADS 256

// ---------------- device scratch ----------------
__device__ int   g_mode64;
__device__ int   g_count[NJ];
__device__ int   g_cursor[NJ];
__device__ int   g_ticket;
__device__ int   g_go;
__device__ int   g_perm[NB];
__device__ float g_cW1[NJ * W1_SZ];          // [j][q][i=0..5][h]
__device__ float g_cW2[NJ * W2_SZ];          // [j][i=0..128][h]
__device__ float g_cVt[NJ * VT_SZ];          // [j][q][o][reordered i]

// ---------------- helpers ----------------
__device__ __forceinline__ float sigmoidf(float v) {
    return 1.0f / (1.0f + __expf(-v));
}
__device__ __forceinline__ unsigned long long pk(float a, float b) {
    unsigned long long r;
    asm("mov.b64 %0, {%1, %2};" : "=l"(r) : "f"(a), "f"(b));
    return r;
}
__device__ __forceinline__ void upk(unsigned long long v, float& lo, float& hi) {
    asm("mov.b64 {%0, %1}, %2;" : "=f"(lo), "=f"(hi) : "l"(v));
}
__device__ __forceinline__ void ffma2(unsigned long long& d,
                                      unsigned long long a,
                                      unsigned long long b) {
    asm("fma.rn.f32x2 %0, %1, %2, %0;" : "+l"(d) : "l"(a), "l"(b));
}

// ================= ONE prologue kernel =================
// count (atomics) -> ticket -> last block scans+resets -> all blocks do the
// weight-combine while waiting -> spin on flag -> scatter.
// All 64 blocks are co-resident (64 << 148 SMs), so the spin cannot deadlock.
__global__ void __launch_bounds__(PREP_THREADS)
k_prep(const int* __restrict__ jw,
       const float* __restrict__ W1, const float* __restrict__ W1a,
       const float* __restrict__ W2, const float* __restrict__ W2a,
       const float* __restrict__ V,  const float* __restrict__ Va) {
    __shared__ int s_any;
    __shared__ int s_cnt[NJ];
    const int tid = threadIdx.x;
    const int b = blockIdx.x * PREP_THREADS + tid;

    if (tid == 0) s_any = 0;
    if (tid < NJ) s_cnt[tid] = 0;
    __syncthreads();

    // int64 little-endian judge ids (0..11) -> all odd words zero
    if (jw[2 * tid + 1] != 0) s_any = 1;   // benign race
    __syncthreads();
    const int m64 = (s_any == 0);

    const int j = m64 ? jw[2 * b] : jw[b];
    atomicAdd(&s_cnt[j], 1);
    __syncthreads();
    if (tid < NJ) {
        if (s_cnt[tid]) atomicAdd(&g_count[tid], s_cnt[tid]);
        __threadfence();
    }
    __syncthreads();

    if (tid == 0) {
        int t = atomicAdd(&g_ticket, 1);
        if (t == PREP_BLOCKS - 1) {            // last block: scan + reset
            int acc = 0;
            #pragma unroll
            for (int k = 0; k < NJ; k++) {
                int c = atomicAdd(&g_count[k], 0);
                g_cursor[k] = acc; acc += c;
                g_count[k] = 0;
            }
            g_mode64 = m64;
            g_ticket = 0;
            __threadfence();
            atomicExch(&g_go, 1);
        }
    }

    // ---- independent work while waiting ----
    const int n1 = NJ * W1_SZ;
    const int n2 = NJ * W2_SZ;
    const int n3 = NJ * VT_SZ;
    const int total = n1 + n2 + n3;
    for (int i = blockIdx.x * PREP_THREADS + tid; i < total;
         i += PREP_BLOCKS * PREP_THREADS) {
        if (i < n1) {
            g_cW1[i] = W1[i % W1_SZ] + W1a[i];
        } else if (i < n1 + n2) {
            int r = i - n1;
            g_cW2[r] = W2[r % W2_SZ] + W2a[r];
        } else {
            int r = i - n1 - n2;
            int ii = r % VT_ROW;
            int rr = r / VT_ROW;          // ((j*NQ+q)*NO+o)
            int o  = rr % NO;
            int qq = (rr / NO) % NQ;
            int jj = rr / (NO * NQ);
            float v = 0.0f;
            int src = (ii < NH2) ? (ii + 1) : ((ii == NH2) ? 0 : -1);
            if (src >= 0)
                v = V[(qq * (NH2 + 1) + src) * NO + o] +
                    Va[((jj * NQ + qq) * (NH2 + 1) + src) * NO + o];
            g_cVt[r] = v;
        }
    }

    if (tid == 0) {
        while (atomicAdd(&g_go, 0) == 0) __nanosleep(64);
    }
    __syncthreads();
    __threadfence();
    int pos = atomicAdd(&g_cursor[j], 1);
    g_perm[pos] = b;
}

// ================= fused MLP =================
__global__ void __launch_bounds__(128)
k_main(const float* __restrict__ x, const int* __restrict__ jw,
       float* __restrict__ out) {
    __shared__ int   sb[GS], sj[GS];
    __shared__ float xs[GS][NQ][NO];
    // union: layer1 out z1 [k=0..127][ZSTR] (4608 f)  then  z2 [28][VT_ROW] (3696 f)
    __shared__ __align__(16) float zbuf[NH1 * ZSTR];
    __shared__ __align__(16) float sVt[VT_SZ];
    __shared__ float lg[GS * NQ][NO];

    const int tid = threadIdx.x;

    if (blockIdx.x == 0 && tid == 0) g_go = 0;     // reset for next replay

    if (tid < GS) {
        int b = g_perm[blockIdx.x * GS + tid];
        sb[tid] = b;
        sj[tid] = g_mode64 ? jw[2 * b] : jw[b];
    }
    __syncthreads();

    const int j0 = sj[0], j1 = sj[1], j2 = sj[2], j3 = sj[3];
    const bool uni = (j0 == j1) & (j1 == j2) & (j2 == j3);

    // async copy of this judge's V^T (consumed only in layer 3)
    if (uni) {
        unsigned sdst = (unsigned)__cvta_generic_to_shared(sVt);
        unsigned long long gsrc;
        const float* p = g_cVt + j0 * VT_SZ;
        asm("cvta.to.global.u64 %0, %1;" : "=l"(gsrc) : "l"(p));
        for (int t = tid; t < VT_SZ / 4; t += 128)
            asm volatile("cp.async.ca.shared.global [%0], [%1], 16;"
                         :: "r"(sdst + t * 16), "l"(gsrc + (unsigned long long)t * 16));
        asm volatile("cp.async.commit_group;");
    }

    for (int t = tid; t < GS * NQ * NO; t += 128) {
        int s = t / (NQ * NO), r = t % (NQ * NO);
        (&xs[0][0][0])[t] = x[sb[s] * (NQ * NO) + r];
    }
    __syncthreads();

    // ---------- layer 1: thread = h column, all (s,q) ----------
    const float* b1[GS] = { g_cW1 + j0 * W1_SZ, g_cW1 + j1 * W1_SZ,
                            g_cW1 + j2 * W1_SZ, g_cW1 + j3 * W1_SZ };
    float a1[GS][NQ];
    #pragma unroll
    for (int q = 0; q < NQ; q++) {
        #pragma unroll
        for (int i = 0; i <= NO; i++) {
            int off = (q * (NO + 1) + i) * NH1 + tid;
            float w[GS];
            w[0] = b1[0][off];
            if (uni) { w[1] = w[0]; w[2] = w[0]; w[3] = w[0]; }
            else     { w[1] = b1[1][off]; w[2] = b1[2][off]; w[3] = b1[3][off]; }
            #pragma unroll
            for (int s = 0; s < GS; s++)
                a1[s][q] = (i == 0) ? w[s] : fmaf(xs[s][q][i - 1], w[s], a1[s][q]);
        }
    }
    // store z1 row [k=tid][s*8+q] (vectorized; stride 36 staggers banks)
    #pragma unroll
    for (int s = 0; s < GS; s++) {
        float* row = zbuf + tid * ZSTR + s * 8;
        float4 v4 = { sigmoidf(a1[s][0]), sigmoidf(a1[s][1]),
                      sigmoidf(a1[s][2]), sigmoidf(a1[s][3]) };
        float2 v2 = { sigmoidf(a1[s][4]), sigmoidf(a1[s][5]) };
        *(float4*)row = v4;
        *(float2*)(row + 4) = v2;
        row[6] = sigmoidf(a1[s][6]);
    }
    __syncthreads();

    // ---------- layer 2: thread = (lx: 4 h-cols, ls: sample), 7q x 4h tile ----------
    const int lx = tid >> 2;            // 0..31 -> h = 4*lx .. 4*lx+3
    const int ls = tid & 3;             // sample
    const float* wbase = g_cW2 + sj[ls] * W2_SZ + 4 * lx;
    const float* zrow = zbuf + ls * 8;

    unsigned long long acc[NQ][2];
    {
        ulonglong2 wb = *(const ulonglong2*)wbase;     // bias row i=0
        #pragma unroll
        for (int q = 0; q < NQ; q++) { acc[q][0] = wb.x; acc[q][1] = wb.y; }
    }
    #pragma unroll 4
    for (int k = 1; k <= NH1; k++) {
        ulonglong2 w = *(const ulonglong2*)(wbase + k * NH2);   // (w0,w1),(w2,w3)
        const float* zr = zrow + (k - 1) * ZSTR;
        float4 za = *(const float4*)zr;        // z[q0..q3]
        float4 zb = *(const float4*)(zr + 4);  // z[q4..q6], pad
        unsigned long long z0 = pk(za.x, za.x), z1 = pk(za.y, za.y),
                           z2 = pk(za.z, za.z), z3 = pk(za.w, za.w),
                           z4 = pk(zb.x, zb.x), z5 = pk(zb.y, zb.y),
                           z6 = pk(zb.z, zb.z);
        ffma2(acc[0][0], z0, w.x); ffma2(acc[0][1], z0, w.y);
        ffma2(acc[1][0], z1, w.x); ffma2(acc[1][1], z1, w.y);
        ffma2(acc[2][0], z2, w.x); ffma2(acc[2][1], z2, w.y);
        ffma2(acc[3][0], z3, w.x); ffma2(acc[3][1], z3, w.y);
        ffma2(acc[4][0], z4, w.x); ffma2(acc[4][1], z4, w.y);
        ffma2(acc[5][0], z5, w.x); ffma2(acc[5][1], z5, w.y);
        ffma2(acc[6][0], z6, w.x); ffma2(acc[6][1], z6, w.y);
    }
    __syncthreads();   // all z1 reads done before z2 overlays zbuf

    // sigmoid -> z2 rows [r=ls*7+q][ 4*lx .. 4*lx+3 ]
    #pragma unroll
    for (int q = 0; q < NQ; q++) {
        float f0, f1, f2, f3;
        upk(acc[q][0], f0, f1);
        upk(acc[q][1], f2, f3);
        float4 o = { sigmoidf(f0), sigmoidf(f1), sigmoidf(f2), sigmoidf(f3) };
        *(float4*)(zbuf + (ls * NQ + q) * VT_ROW + 4 * lx) = o;
    }
    if (tid < GS * NQ) {                 // bias at [128], zero pads
        float* row = zbuf + tid * VT_ROW;
        row[NH2] = 1.0f; row[NH2 + 1] = 0.0f; row[NH2 + 2] = 0.0f; row[NH2 + 3] = 0.0f;
    }
    if (uni) asm volatile("cp.async.wait_group 0;" ::: "memory");
    __syncthreads();

    // ---------- layer 3: logits ----------
    for (int t = tid; t < GS * NQ * NO; t += 128) {
        int s = t / (NQ * NO), r = t % (NQ * NO), q = r / NO, o = r % NO;
        const ulonglong2* vz = (const ulonglong2*)(zbuf + (s * NQ + q) * VT_ROW);
        const ulonglong2* vv = uni
            ? (const ulonglong2*)(sVt + (q * NO + o) * VT_ROW)
            : (const ulonglong2*)(g_cVt + (sj[s] * NQ * NO + q * NO + o) * VT_ROW);
        unsigned long long acc0 = 0ULL, acc1 = 0ULL;
        #pragma unroll
        for (int k = 0; k < VT_ROW / 4; k++) {
            ulonglong2 a = vz[k], bb = vv[k];
            ffma2(acc0, a.x, bb.x);
            ffma2(acc1, a.y, bb.y);
        }
        float f0, f1, f2, f3;
        upk(acc0, f0, f1);
        upk(acc1, f2, f3);
        lg[s * NQ + q][o] = (f0 + f1) + (f2 + f3);
    }
    __syncthreads();

    // ---------- softmax + store ----------
    if (tid < GS * NQ) {
        int s = tid / NQ, q = tid % NQ;
        float m = lg[tid][0];
        #pragma unroll
        for (int o = 1; o < NO; o++) m = fmaxf(m, lg[tid][o]);
        float e[NO], sum = 0.f;
        #pragma unroll
        for (int o = 0; o < NO; o++) { e[o] = __expf(lg[tid][o] - m); sum += e[o]; }
        float inv = 1.0f / sum;
        float* op = out + (sb[s] * NQ + q) * NO;
        #pragma unroll
        for (int o = 0; o < NO; o++) op[o] = e[o] * inv;
    }
}

// ---------------- launch ----------------
extern "C" void kernel_launch(void* const* d_in, const int* in_sizes, int n_in,
                              void* d_out, int out_size) {
    const float* x   = (const float*)d_in[0];
    const int*   jw  = (const int*)  d_in[1];
    const float* W1  = (const float*)d_in[2];
    const float* W1a = (const float*)d_in[3];
    const float* W2  = (const float*)d_in[4];
    const float* W2a = (const float*)d_in[5];
    const float* V   = (const float*)d_in[6];
    const float* Va  = (const float*)d_in[7];
    float* out = (float*)d_out;

    k_prep<<<PREP_BLOCKS, PREP_THREADS>>>(jw, W1, W1a, W2, W2a, V, Va);
    k_main<<<NBLOCKS, 128>>>(x, jw, out);
}

// round 9
// speedup vs baseline: 1.4238x; 1.4238x over previous
#include <cuda_runtime.h>

#define NB   16384
#define NJ   12
#define NQ   7
#define NO   5
#define NH1  128
#define NH2  128
#define GS   4
#define NBLOCKS (NB / GS)

#define W1_SZ (NQ * (NO + 1) * NH1)     // 5376
#define W2_SZ ((NH1 + 1) * NH2)         // 16512
#define VT_ROW 132                      // [bias, w_1..w_128, 0,0,0]
#define VT_SZ (NQ * NO * VT_ROW)        // 4620
#define ZSTR 28                         // z1 row stride in floats ([k][q][s])

#define PREP_BLOCKS 64
#define PREP_THREADS 256

// ---------------- device scratch ----------------
__device__ int   g_mode64;
__device__ int   g_count[NJ];           // zero-initialized; re-zeroed by k_scan
__device__ int   g_cursor[NJ];
__device__ int   g_perm[NB];
__device__ float g_cW1[NJ * W1_SZ];     // [j][q][i=0..5][h]
__device__ float g_cW2[NJ * W2_SZ];     // [j][i=0..128][h]
__device__ float g_cVt[NJ * VT_SZ];     // [j][q][o][i=0..128,pad]

// ---------------- helpers ----------------
__device__ __forceinline__ float sigmoidf(float v) {
    return 1.0f / (1.0f + __expf(-v));
}
__device__ __forceinline__ unsigned long long pk(float a, float b) {
    unsigned long long r;
    asm("mov.b64 %0, {%1, %2};" : "=l"(r) : "f"(a), "f"(b));
    return r;
}
__device__ __forceinline__ void upk(unsigned long long v, float& lo, float& hi) {
    asm("mov.b64 {%0, %1}, %2;" : "=f"(lo), "=f"(hi) : "l"(v));
}
__device__ __forceinline__ void ffma2(unsigned long long& d,
                                      unsigned long long a,
                                      unsigned long long b) {
    asm("fma.rn.f32x2 %0, %1, %2, %0;" : "+l"(d) : "l"(a), "l"(b));
}

// ---------- detect judge-id dtype from the first 512 words (in-bounds both modes) ----------
__device__ __forceinline__ int detect_m64(const int* __restrict__ jw, int tid) {
    __shared__ int s_any;
    if (tid == 0) s_any = 0;
    __syncthreads();
    // int64 little-endian ids (0..11): every odd word is 0. int32 ids: ~surely not.
    if (jw[2 * (tid & 255) + 1] != 0) s_any = 1;   // benign race
    __syncthreads();
    return (s_any == 0);
}

// ================= prologue kernel 1: histogram + dtype + weight combine =================
__global__ void __launch_bounds__(PREP_THREADS)
k_countw(const int* __restrict__ jw,
         const float* __restrict__ W1, const float* __restrict__ W1a,
         const float* __restrict__ W2, const float* __restrict__ W2a,
         const float* __restrict__ V,  const float* __restrict__ Va) {
    __shared__ int s_cnt[NJ];
    const int tid = threadIdx.x;
    const int b = blockIdx.x * PREP_THREADS + tid;   // one sample per thread

    const int m64 = detect_m64(jw, tid);
    if (blockIdx.x == 0 && tid == 0) g_mode64 = m64;

    if (tid < NJ) s_cnt[tid] = 0;
    __syncthreads();
    const int j = m64 ? jw[2 * b] : jw[b];
    atomicAdd(&s_cnt[j], 1);
    __syncthreads();
    if (tid < NJ && s_cnt[tid]) atomicAdd(&g_count[tid], s_cnt[tid]);

    // ---- weight combine (bulk of this kernel) ----
    const int n1 = NJ * W1_SZ;
    const int n2 = NJ * W2_SZ;
    const int n3 = NJ * VT_SZ;
    const int total = n1 + n2 + n3;
    for (int i = blockIdx.x * PREP_THREADS + tid; i < total;
         i += PREP_BLOCKS * PREP_THREADS) {
        if (i < n1) {
            g_cW1[i] = W1[i % W1_SZ] + W1a[i];
        } else if (i < n1 + n2) {
            int r = i - n1;
            g_cW2[r] = W2[r % W2_SZ] + W2a[r];
        } else {
            int r = i - n1 - n2;
            int ii = r % VT_ROW;          // 0 = bias, 1..128 = weights
            int rr = r / VT_ROW;          // ((j*NQ+q)*NO+o)
            int o  = rr % NO;
            int qq = (rr / NO) % NQ;
            int jj = rr / (NO * NQ);
            float v = 0.0f;               // zero pads
            if (ii <= NH2)
                v = V[(qq * (NH2 + 1) + ii) * NO + o] +
                    Va[((jj * NQ + qq) * (NH2 + 1) + ii) * NO + o];
            g_cVt[r] = v;
        }
    }
}

// ================= prologue kernel 2: exclusive scan + reset counts =================
__global__ void k_scan() {
    if (threadIdx.x == 0) {
        int acc = 0;
        #pragma unroll
        for (int k = 0; k < NJ; k++) {
            g_cursor[k] = acc;
            acc += g_count[k];
            g_count[k] = 0;               // ready for next graph replay
        }
    }
}

// ================= prologue kernel 3: scatter =================
__global__ void __launch_bounds__(PREP_THREADS)
k_scatter(const int* __restrict__ jw) {
    const int tid = threadIdx.x;
    const int b = blockIdx.x * PREP_THREADS + tid;
    const int m64 = g_mode64;
    const int j = m64 ? jw[2 * b] : jw[b];
    int pos = atomicAdd(&g_cursor[j], 1);
    g_perm[pos] = b;
}

// ================= fused MLP, GS same-judge samples per block =================
__global__ void __launch_bounds__(128, 6)
k_main(const float* __restrict__ x, const int* __restrict__ jw,
       float* __restrict__ out) {
    __shared__ int   sb[GS], sj[GS];
    __shared__ __align__(16) float xs2[NQ * NO * GS];    // [q][o][s0..s3]
    // union: layer1 z1 [k=0..127][q][s] (3584 f)  then  z2 [28][VT_ROW] (3696 f)
    __shared__ __align__(16) float zbuf[GS * NQ * VT_ROW];
    __shared__ __align__(16) float sVt[VT_SZ];           // this judge's V^T
    __shared__ float lg[GS * NQ][NO];

    const int tid = threadIdx.x;

    if (tid < GS) {
        int b = g_perm[blockIdx.x * GS + tid];
        sb[tid] = b;
        sj[tid] = g_mode64 ? jw[2 * b] : jw[b];
    }
    __syncthreads();

    const int j0 = sj[0], j1 = sj[1], j2 = sj[2], j3 = sj[3];
    const bool uni = (j0 == j1) & (j1 == j2) & (j2 == j3);

    // async prefetch of this judge's V^T (consumed only in layer 3)
    if (uni) {
        unsigned sdst = (unsigned)__cvta_generic_to_shared(sVt);
        unsigned long long gsrc;
        const float* p = g_cVt + j0 * VT_SZ;
        asm("cvta.to.global.u64 %0, %1;" : "=l"(gsrc) : "l"(p));
        for (int t = tid; t < VT_SZ / 4; t += 128)
            asm volatile("cp.async.ca.shared.global [%0], [%1], 16;"
                         :: "r"(sdst + t * 16), "l"(gsrc + (unsigned long long)t * 16));
        asm volatile("cp.async.commit_group;");
    }

    // stage x transposed: xs2[(q*5+o)*4 + s]
    for (int t = tid; t < GS * NQ * NO; t += 128) {
        int s = t / (NQ * NO), r = t % (NQ * NO);
        xs2[r * GS + s] = x[sb[s] * (NQ * NO) + r];
    }
    __syncthreads();

    // ---------- layer 1: thread = h column, all (s,q) ----------
    const float* b1[GS] = { g_cW1 + j0 * W1_SZ, g_cW1 + j1 * W1_SZ,
                            g_cW1 + j2 * W1_SZ, g_cW1 + j3 * W1_SZ };
    float a1[GS][NQ];
    #pragma unroll
    for (int q = 0; q < NQ; q++) {
        {   // i = 0 (bias)
            int off = (q * (NO + 1)) * NH1 + tid;
            float w[GS];
            w[0] = b1[0][off];
            if (uni) { w[1] = w[0]; w[2] = w[0]; w[3] = w[0]; }
            else     { w[1] = b1[1][off]; w[2] = b1[2][off]; w[3] = b1[3][off]; }
            #pragma unroll
            for (int s = 0; s < GS; s++) a1[s][q] = w[s];
        }
        #pragma unroll
        for (int i = 1; i <= NO; i++) {
            int off = (q * (NO + 1) + i) * NH1 + tid;
            float w[GS];
            w[0] = b1[0][off];
            if (uni) { w[1] = w[0]; w[2] = w[0]; w[3] = w[0]; }
            else     { w[1] = b1[1][off]; w[2] = b1[2][off]; w[3] = b1[3][off]; }
            float4 xv = *(const float4*)(xs2 + (q * NO + i - 1) * GS);
            a1[0][q] = fmaf(xv.x, w[0], a1[0][q]);
            a1[1][q] = fmaf(xv.y, w[1], a1[1][q]);
            a1[2][q] = fmaf(xv.z, w[2], a1[2][q]);
            a1[3][q] = fmaf(xv.w, w[3], a1[3][q]);
        }
    }
    // store z1 row [k=tid][q][s] as 7 x STS.128 (conflict-free, 16B aligned)
    #pragma unroll
    for (int q = 0; q < NQ; q++) {
        float4 v = { sigmoidf(a1[0][q]), sigmoidf(a1[1][q]),
                     sigmoidf(a1[2][q]), sigmoidf(a1[3][q]) };
        *(float4*)(zbuf + tid * ZSTR + q * 4) = v;
    }
    __syncthreads();

    // ---------- layer 2: thread = h column, f32x2 s-packed accumulators ----------
    const float* b2[GS] = { g_cW2 + j0 * W2_SZ, g_cW2 + j1 * W2_SZ,
                            g_cW2 + j2 * W2_SZ, g_cW2 + j3 * W2_SZ };
    unsigned long long a01[NQ], a23[NQ];
    {
        float w[GS];
        w[0] = b2[0][tid];  // bias row i=0
        if (uni) { w[1] = w[0]; w[2] = w[0]; w[3] = w[0]; }
        else     { w[1] = b2[1][tid]; w[2] = b2[2][tid]; w[3] = b2[3][tid]; }
        unsigned long long p01 = pk(w[0], w[1]);
        unsigned long long p23 = pk(w[2], w[3]);
        #pragma unroll
        for (int q = 0; q < NQ; q++) { a01[q] = p01; a23[q] = p23; }
    }
    #pragma unroll 4
    for (int i = 1; i <= NH1; i++) {
        int off = i * NH2 + tid;
        float w0 = b2[0][off];
        unsigned long long p01, p23;
        if (uni) {
            p01 = pk(w0, w0);
            p23 = p01;
        } else {
            float w1v = b2[1][off], w2v = b2[2][off], w3v = b2[3][off];
            p01 = pk(w0, w1v);
            p23 = pk(w2v, w3v);
        }
        const ulonglong2* zr = (const ulonglong2*)(zbuf + (i - 1) * ZSTR);
        #pragma unroll
        for (int q = 0; q < NQ; q++) {
            ulonglong2 z = zr[q];      // {z[s0],z[s1]}, {z[s2],z[s3]}
            ffma2(a01[q], z.x, p01);
            ffma2(a23[q], z.y, p23);
        }
    }
    __syncthreads();   // all z1 reads done before z2 overlays zbuf

    #pragma unroll
    for (int q = 0; q < NQ; q++) {
        float v0, v1, v2, v3;
        upk(a01[q], v0, v1);
        upk(a23[q], v2, v3);
        zbuf[(0 * NQ + q) * VT_ROW + 1 + tid] = sigmoidf(v0);
        zbuf[(1 * NQ + q) * VT_ROW + 1 + tid] = sigmoidf(v1);
        zbuf[(2 * NQ + q) * VT_ROW + 1 + tid] = sigmoidf(v2);
        zbuf[(3 * NQ + q) * VT_ROW + 1 + tid] = sigmoidf(v3);
    }
    if (tid < GS * NQ) {                 // bias + zero pads
        float* row = zbuf + tid * VT_ROW;
        row[0] = 1.0f; row[129] = 0.0f; row[130] = 0.0f; row[131] = 0.0f;
    }
    if (uni) asm volatile("cp.async.wait_group 0;" ::: "memory");
    __syncthreads();

    // ---------- layer 3: logits via smem-cached transposed V ----------
    for (int t = tid; t < GS * NQ * NO; t += 128) {
        int s = t / (NQ * NO), r = t % (NQ * NO), q = r / NO, o = r % NO;
        const ulonglong2* vz = (const ulonglong2*)(zbuf + (s * NQ + q) * VT_ROW);
        const ulonglong2* vv = uni
            ? (const ulonglong2*)(sVt + (q * NO + o) * VT_ROW)
            : (const ulonglong2*)(g_cVt + (sj[s] * NQ * NO + q * NO + o) * VT_ROW);
        unsigned long long acc0 = 0ULL, acc1 = 0ULL;
        #pragma unroll
        for (int k = 0; k < VT_ROW / 4; k++) {
            ulonglong2 a = vz[k], bb = vv[k];
            ffma2(acc0, a.x, bb.x);
            ffma2(acc1, a.y, bb.y);
        }
        float f0, f1, f2, f3;
        upk(acc0, f0, f1);
        upk(acc1, f2, f3);
        lg[s * NQ + q][o] = (f0 + f1) + (f2 + f3);
    }
    __syncthreads();

    // ---------- softmax + store ----------
    if (tid < GS * NQ) {
        int s = tid / NQ, q = tid % NQ;
        float m = lg[tid][0];
        #pragma unroll
        for (int o = 1; o < NO; o++) m = fmaxf(m, lg[tid][o]);
        float e[NO], sum = 0.f;
        #pragma unroll
        for (int o = 0; o < NO; o++) { e[o] = __expf(lg[tid][o] - m); sum += e[o]; }
        float inv = 1.0f / sum;
        float* op = out + (sb[s] * NQ + q) * NO;
        #pragma unroll
        for (int o = 0; o < NO; o++) op[o] = e[o] * inv;
    }
}

// ---------------- launch ----------------
extern "C" void kernel_launch(void* const* d_in, const int* in_sizes, int n_in,
                              void* d_out, int out_size) {
    const float* x   = (const float*)d_in[0];
    const int*   jw  = (const int*)  d_in[1];
    const float* W1  = (const float*)d_in[2];
    const float* W1a = (const float*)d_in[3];
    const float* W2  = (const float*)d_in[4];
    const float* W2a = (const float*)d_in[5];
    const float* V   = (const float*)d_in[6];
    const float* Va  = (const float*)d_in[7];
    float* out = (float*)d_out;

    k_countw <<<PREP_BLOCKS, PREP_THREADS>>>(jw, W1, W1a, W2, W2a, V, Va);
    k_scan   <<<1, 32>>>();
    k_scatter<<<PREP_BLOCKS, PREP_THREADS>>>(jw);
    k_main   <<<NBLOCKS, 128>>>(x, jw, out);
}

// round 12
// speedup vs baseline: 1.6001x; 1.1238x over previous
#include <cuda_runtime.h>

#define NB   16384
#define NJ   12
#define NQ   7
#define NO   5
#define NH1  128
#define NH2  128
#define GS   4
#define NBLOCKS (NB / GS)

#define W1_SZ (NQ * (NO + 1) * NH1)     // 5376
#define W2_SZ ((NH1 + 1) * NH2)         // 16512
#define VT_ROW 132                      // [bias, w_1..w_128, 0,0,0]
#define VT_SZ (NQ * NO * VT_ROW)        // 4620
#define ZSTR 28                         // z1 row stride in floats ([k][q][s])

#define PREP_BLOCKS 64
#define PREP_THREADS 256

// ---------------- device scratch ----------------
__device__ int   g_mode64;
__device__ int   g_count[NJ];           // zero-initialized; re-zeroed by k_scan
__device__ int   g_cursor[NJ];
__device__ int   g_perm[NB];
__device__ float g_cW1[NJ * W1_SZ];     // [j][q][i=0..5][h]
__device__ float g_cW2[NJ * W2_SZ];     // [j][i=0..128][h]
__device__ float g_cVt[NJ * VT_SZ];     // [j][q][o][i=0..128,pad]

// ---------------- helpers ----------------
__device__ __forceinline__ float sigmoidf(float v) {
    return 1.0f / (1.0f + __expf(-v));
}
__device__ __forceinline__ unsigned long long pk(float a, float b) {
    unsigned long long r;
    asm("mov.b64 %0, {%1, %2};" : "=l"(r) : "f"(a), "f"(b));
    return r;
}
__device__ __forceinline__ void upk(unsigned long long v, float& lo, float& hi) {
    asm("mov.b64 {%0, %1}, %2;" : "=f"(lo), "=f"(hi) : "l"(v));
}
__device__ __forceinline__ void ffma2(unsigned long long& d,
                                      unsigned long long a,
                                      unsigned long long b) {
    asm("fma.rn.f32x2 %0, %1, %2, %0;" : "+l"(d) : "l"(a), "l"(b));
}

// ---------- detect judge-id dtype from the first 512 words ----------
__device__ __forceinline__ int detect_m64(const int* __restrict__ jw, int tid) {
    __shared__ int s_any;
    if (tid == 0) s_any = 0;
    __syncthreads();
    // int64 little-endian ids (0..11): every odd word is 0.
    if (jw[2 * (tid & 255) + 1] != 0) s_any = 1;   // benign race
    __syncthreads();
    return (s_any == 0);
}

// ================= prologue 1: histogram + dtype + weight combine =================
__global__ void __launch_bounds__(PREP_THREADS)
k_countw(const int* __restrict__ jw,
         const float* __restrict__ W1, const float* __restrict__ W1a,
         const float* __restrict__ W2, const float* __restrict__ W2a,
         const float* __restrict__ V,  const float* __restrict__ Va) {
    __shared__ int s_cnt[NJ];
    const int tid = threadIdx.x;
    const int b = blockIdx.x * PREP_THREADS + tid;

    const int m64 = detect_m64(jw, tid);
    if (blockIdx.x == 0 && tid == 0) g_mode64 = m64;

    if (tid < NJ) s_cnt[tid] = 0;
    __syncthreads();
    const int j = m64 ? jw[2 * b] : jw[b];
    atomicAdd(&s_cnt[j], 1);
    __syncthreads();
    if (tid < NJ && s_cnt[tid]) atomicAdd(&g_count[tid], s_cnt[tid]);

    const int n1 = NJ * W1_SZ;
    const int n2 = NJ * W2_SZ;
    const int n3 = NJ * VT_SZ;
    const int total = n1 + n2 + n3;
    for (int i = blockIdx.x * PREP_THREADS + tid; i < total;
         i += PREP_BLOCKS * PREP_THREADS) {
        if (i < n1) {
            g_cW1[i] = W1[i % W1_SZ] + W1a[i];
        } else if (i < n1 + n2) {
            int r = i - n1;
            g_cW2[r] = W2[r % W2_SZ] + W2a[r];
        } else {
            int r = i - n1 - n2;
            int ii = r % VT_ROW;          // 0 = bias, 1..128 = weights
            int rr = r / VT_ROW;          // ((j*NQ+q)*NO+o)
            int o  = rr % NO;
            int qq = (rr / NO) % NQ;
            int jj = rr / (NO * NQ);
            float v = 0.0f;
            if (ii <= NH2)
                v = V[(qq * (NH2 + 1) + ii) * NO + o] +
                    Va[((jj * NQ + qq) * (NH2 + 1) + ii) * NO + o];
            g_cVt[r] = v;
        }
    }
}

// ================= prologue 2: scan + reset =================
__global__ void k_scan() {
    if (threadIdx.x == 0) {
        int acc = 0;
        #pragma unroll
        for (int k = 0; k < NJ; k++) {
            g_cursor[k] = acc;
            acc += g_count[k];
            g_count[k] = 0;
        }
    }
}

// ================= prologue 3: scatter =================
__global__ void __launch_bounds__(PREP_THREADS)
k_scatter(const int* __restrict__ jw) {
    const int tid = threadIdx.x;
    const int b = blockIdx.x * PREP_THREADS + tid;
    const int j = g_mode64 ? jw[2 * b] : jw[b];
    int pos = atomicAdd(&g_cursor[j], 1);
    g_perm[pos] = b;
}

// ================= templated MLP body (UNI = all 4 samples same judge) =================
template <bool UNI>
__device__ __forceinline__ void mlp_body(
    int tid, const int* __restrict__ sj, const int* __restrict__ sb,
    const float* __restrict__ xs2, float* __restrict__ zbuf,
    const float* __restrict__ sVt, float (*__restrict__ lg)[NO],
    float* __restrict__ out) {

    const int j0 = sj[0];
    const float* b1_0 = g_cW1 + j0 * W1_SZ;
    const float* b1_1 = UNI ? b1_0 : g_cW1 + sj[1] * W1_SZ;
    const float* b1_2 = UNI ? b1_0 : g_cW1 + sj[2] * W1_SZ;
    const float* b1_3 = UNI ? b1_0 : g_cW1 + sj[3] * W1_SZ;

    // ---------- layer 1: thread = h column, all (s,q) ----------
    float a1[GS][NQ];
    #pragma unroll
    for (int q = 0; q < NQ; q++) {
        {   // i = 0 (bias)
            int off = (q * (NO + 1)) * NH1 + tid;
            a1[0][q] = b1_0[off];
            a1[1][q] = UNI ? a1[0][q] : b1_1[off];
            a1[2][q] = UNI ? a1[0][q] : b1_2[off];
            a1[3][q] = UNI ? a1[0][q] : b1_3[off];
        }
        #pragma unroll
        for (int i = 1; i <= NO; i++) {
            int off = (q * (NO + 1) + i) * NH1 + tid;
            float w0 = b1_0[off];
            float w1 = UNI ? w0 : b1_1[off];
            float w2 = UNI ? w0 : b1_2[off];
            float w3 = UNI ? w0 : b1_3[off];
            float4 xv = *(const float4*)(xs2 + (q * NO + i - 1) * GS);
            a1[0][q] = fmaf(xv.x, w0, a1[0][q]);
            a1[1][q] = fmaf(xv.y, w1, a1[1][q]);
            a1[2][q] = fmaf(xv.z, w2, a1[2][q]);
            a1[3][q] = fmaf(xv.w, w3, a1[3][q]);
        }
    }
    // store z1 row [k=tid][q][s] as 7 x STS.128 (conflict-free)
    #pragma unroll
    for (int q = 0; q < NQ; q++) {
        float4 v = { sigmoidf(a1[0][q]), sigmoidf(a1[1][q]),
                     sigmoidf(a1[2][q]), sigmoidf(a1[3][q]) };
        *(float4*)(zbuf + tid * ZSTR + q * 4) = v;
    }
    __syncthreads();

    // ---------- layer 2: thread = h column, f32x2 s-packed accumulators ----------
    const float* b2_0 = g_cW2 + j0 * W2_SZ;
    const float* b2_1 = UNI ? b2_0 : g_cW2 + sj[1] * W2_SZ;
    const float* b2_2 = UNI ? b2_0 : g_cW2 + sj[2] * W2_SZ;
    const float* b2_3 = UNI ? b2_0 : g_cW2 + sj[3] * W2_SZ;

    unsigned long long a01[NQ], a23[NQ];
    {
        float w0 = b2_0[tid];  // bias row i=0
        unsigned long long p01, p23;
        if (UNI) { p01 = pk(w0, w0); p23 = p01; }
        else     { p01 = pk(w0, b2_1[tid]); p23 = pk(b2_2[tid], b2_3[tid]); }
        #pragma unroll
        for (int q = 0; q < NQ; q++) { a01[q] = p01; a23[q] = p23; }
    }
    #pragma unroll 4
    for (int i = 1; i <= NH1; i++) {
        int off = i * NH2 + tid;
        float w0 = b2_0[off];
        unsigned long long p01, p23;
        if (UNI) { p01 = pk(w0, w0); p23 = p01; }
        else     { p01 = pk(w0, b2_1[off]); p23 = pk(b2_2[off], b2_3[off]); }
        const ulonglong2* zr = (const ulonglong2*)(zbuf + (i - 1) * ZSTR);
        #pragma unroll
        for (int q = 0; q < NQ; q++) {
            ulonglong2 z = zr[q];      // {z[s0],z[s1]}, {z[s2],z[s3]}
            ffma2(a01[q], z.x, p01);
            ffma2(a23[q], z.y, p23);
        }
    }
    __syncthreads();   // all z1 reads done before z2 overlays zbuf

    #pragma unroll
    for (int q = 0; q < NQ; q++) {
        float v0, v1, v2, v3;
        upk(a01[q], v0, v1);
        upk(a23[q], v2, v3);
        zbuf[(0 * NQ + q) * VT_ROW + 1 + tid] = sigmoidf(v0);
        zbuf[(1 * NQ + q) * VT_ROW + 1 + tid] = sigmoidf(v1);
        zbuf[(2 * NQ + q) * VT_ROW + 1 + tid] = sigmoidf(v2);
        zbuf[(3 * NQ + q) * VT_ROW + 1 + tid] = sigmoidf(v3);
    }
    if (tid < GS * NQ) {                 // bias + zero pads
        float* row = zbuf + tid * VT_ROW;
        row[0] = 1.0f; row[129] = 0.0f; row[130] = 0.0f; row[131] = 0.0f;
    }
    if (UNI) asm volatile("cp.async.wait_group 0;" ::: "memory");
    __syncthreads();

    // ---------- layer 3: logits ----------
    for (int t = tid; t < GS * NQ * NO; t += 128) {
        int s = t / (NQ * NO), r = t % (NQ * NO), q = r / NO, o = r % NO;
        const ulonglong2* vz = (const ulonglong2*)(zbuf + (s * NQ + q) * VT_ROW);
        const ulonglong2* vv = UNI
            ? (const ulonglong2*)(sVt + (q * NO + o) * VT_ROW)
            : (const ulonglong2*)(g_cVt + (sj[s] * NQ * NO + q * NO + o) * VT_ROW);
        unsigned long long acc0 = 0ULL, acc1 = 0ULL;
        #pragma unroll
        for (int k = 0; k < VT_ROW / 4; k++) {
            ulonglong2 a = vz[k], bb = vv[k];
            ffma2(acc0, a.x, bb.x);
            ffma2(acc1, a.y, bb.y);
        }
        float f0, f1, f2, f3;
        upk(acc0, f0, f1);
        upk(acc1, f2, f3);
        lg[s * NQ + q][o] = (f0 + f1) + (f2 + f3);
    }
    __syncthreads();

    // ---------- softmax + store ----------
    if (tid < GS * NQ) {
        int s = tid / NQ, q = tid % NQ;
        float m = lg[tid][0];
        #pragma unroll
        for (int o = 1; o < NO; o++) m = fmaxf(m, lg[tid][o]);
        float e[NO], sum = 0.f;
        #pragma unroll
        for (int o = 0; o < NO; o++) { e[o] = __expf(lg[tid][o] - m); sum += e[o]; }
        float inv = 1.0f / sum;
        float* op = out + (sb[s] * NQ + q) * NO;
        #pragma unroll
        for (int o = 0; o < NO; o++) op[o] = e[o] * inv;
    }
}

// ================= fused MLP, GS same-judge samples per block =================
__global__ void __launch_bounds__(128)
k_main(const float* __restrict__ x, const int* __restrict__ jw,
       float* __restrict__ out) {
    __shared__ int   sb[GS], sj[GS];
    __shared__ __align__(16) float xs2[NQ * NO * GS];    // [q][o][s0..s3]
    // union: layer1 z1 [k][q][s] (3584 f)  then  z2 [28][VT_ROW] (3696 f)
    __shared__ __align__(16) float zbuf[GS * NQ * VT_ROW];
    __shared__ __align__(16) float sVt[VT_SZ];           // this judge's V^T
    __shared__ float lg[GS * NQ][NO];

    const int tid = threadIdx.x;

    if (tid < GS) {
        int b = g_perm[blockIdx.x * GS + tid];
        sb[tid] = b;
        sj[tid] = g_mode64 ? jw[2 * b] : jw[b];
    }
    __syncthreads();

    const bool uni = (sj[0] == sj[1]) & (sj[1] == sj[2]) & (sj[2] == sj[3]);

    // async prefetch of this judge's V^T (consumed only in layer 3)
    if (uni) {
        unsigned sdst = (unsigned)__cvta_generic_to_shared(sVt);
        unsigned long long gsrc;
        const float* p = g_cVt + sj[0] * VT_SZ;
        asm("cvta.to.global.u64 %0, %1;" : "=l"(gsrc) : "l"(p));
        for (int t = tid; t < VT_SZ / 4; t += 128)
            asm volatile("cp.async.ca.shared.global [%0], [%1], 16;"
                         :: "r"(sdst + t * 16), "l"(gsrc + (unsigned long long)t * 16));
        asm volatile("cp.async.commit_group;");
    }

    // stage x transposed: xs2[(q*5+o)*4 + s]
    for (int t = tid; t < GS * NQ * NO; t += 128) {
        int s = t / (NQ * NO), r = t % (NQ * NO);
        xs2[r * GS + s] = x[sb[s] * (NQ * NO) + r];
    }
    __syncthreads();

    if (uni) mlp_body<true >(tid, sj, sb, xs2, zbuf, sVt, lg, out);
    else     mlp_body<false>(tid, sj, sb, xs2, zbuf, sVt, lg, out);
}

// ---------------- launch ----------------
extern "C" void kernel_launch(void* const* d_in, const int* in_sizes, int n_in,
                              void* d_out, int out_size) {
    const float* x   = (const float*)d_in[0];
    const int*   jw  = (const int*)  d_in[1];
    const float* W1  = (const float*)d_in[2];
    const float* W1a = (const float*)d_in[3];
    const float* W2  = (const float*)d_in[4];
    const float* W2a = (const float*)d_in[5];
    const float* V   = (const float*)d_in[6];
    const float* Va  = (const float*)d_in[7];
    float* out = (float*)d_out;

    k_countw <<<PREP_BLOCKS, PREP_THREADS>>>(jw, W1, W1a, W2, W2a, V, Va);
    k_scan   <<<1, 32>>>();
    k_scatter<<<PREP_BLOCKS, PREP_THREADS>>>(jw);
    k_main   <<<NBLOCKS, 128>>>(x, jw, out);
}